// round 1
// baseline (speedup 1.0000x reference)
#include <cuda_runtime.h>
#include <cstdint>

// Problem constants (fixed shapes per reference setup_inputs)
#define B_    2
#define H_    32
#define S_    4096
#define D_    128
#define U_    16
#define GROUP_ 128
#define TQ    3968        // S - RESID - (S % GROUP)
#define NG    31          // TQ / GROUP
#define RROWS 257         // 2*RESID + 1

// Output region offsets (float32 elements, concatenated in reference return order)
static constexpr size_t LEN_QK  = (size_t)B_ * H_ * (TQ / 4) * D_;   // 8,126,464
static constexpr size_t LEN_SC  = (size_t)B_ * H_ * NG * D_;         // 253,952
static constexpr size_t LEN_QV  = (size_t)B_ * H_ * (D_ / 4) * TQ;   // 8,126,464
static constexpr size_t LEN_VSC = (size_t)B_ * H_ * TQ;              // 253,952
static constexpr size_t LEN_R   = (size_t)B_ * H_ * RROWS * D_;      // 2,105,344
static constexpr size_t LEN_F   = (size_t)B_ * H_ * S_ * D_;         // 33,554,432

static constexpr size_t OFF_QK = 0;
static constexpr size_t OFF_KS = OFF_QK + LEN_QK;
static constexpr size_t OFF_KM = OFF_KS + LEN_SC;
static constexpr size_t OFF_QV = OFF_KM + LEN_SC;
static constexpr size_t OFF_VS = OFF_QV + LEN_QV;
static constexpr size_t OFF_VM = OFF_VS + LEN_VSC;
static constexpr size_t OFF_KR = OFF_VM + LEN_VSC;
static constexpr size_t OFF_VR = OFF_KR + LEN_R;
static constexpr size_t OFF_KF = OFF_VR + LEN_R;
static constexpr size_t OFF_VF = OFF_KF + LEN_F;

__device__ __forceinline__ int quant_code(float x, float mn, float inv_is_not_used_scale) {
    // unused helper placeholder (kept out of hot path)
    return 0;
}

// ---------------------------------------------------------------------------
// K quantization: groups of 128 along seq, per (b,h,g,d). Pack 4 seq codes/u16.
// 512 threads: thread = (d in 0..127, q in 0..3), q owns 32 seq rows in regs.
// ---------------------------------------------------------------------------
__global__ __launch_bounds__(512, 2)
void k_quant_kernel(const float* __restrict__ k, float* __restrict__ out) {
    const int g = blockIdx.x, h = blockIdx.y, b = blockIdx.z;
    const int d = threadIdx.x & 127;
    const int q = threadIdx.x >> 7;          // 0..3, each owns 32 seq rows

    const float* base = k + (((size_t)(b * H_ + h)) * S_ + (size_t)g * GROUP_) * D_;

    float vals[32];
    float mn = 3.4e38f, mx = -3.4e38f;
#pragma unroll
    for (int i = 0; i < 32; i++) {
        float x = __ldg(base + ((size_t)(q * 32 + i)) * D_ + d);
        vals[i] = x;
        mn = fminf(mn, x);
        mx = fmaxf(mx, x);
    }

    __shared__ float smn[4][128];
    __shared__ float smx[4][128];
    smn[q][d] = mn;
    smx[q][d] = mx;
    __syncthreads();
    mn = fminf(fminf(smn[0][d], smn[1][d]), fminf(smn[2][d], smn[3][d]));
    mx = fmaxf(fmaxf(smx[0][d], smx[1][d]), fmaxf(smx[2][d], smx[3][d]));

    // scale = max((mx-mn)/15, 1e-6) with IEEE division to match JAX bitwise
    const float scale = fmaxf(__fdiv_rn(mx - mn, 15.0f), 1e-6f);

    if (q == 0) {
        size_t si = (((size_t)(b * H_ + h)) * NG + g) * D_ + d;
        out[OFF_KS + si] = scale;
        out[OFF_KM + si] = mn;
    }

    // pack: this thread produces 8 uint16 rows (seq-packed), coalesced across d
    float* __restrict__ po = out + OFF_QK;
    const size_t rowbase = ((size_t)(b * H_ + h)) * (TQ / 4) + (size_t)g * 32 + (size_t)q * 8;
#pragma unroll
    for (int j = 0; j < 8; j++) {
        unsigned p = 0;
#pragma unroll
        for (int n = 0; n < 4; n++) {
            float qf = rintf(__fdiv_rn(vals[j * 4 + n] - mn, scale));
            int c = (int)qf;
            c = c < 0 ? 0 : (c > 15 ? 15 : c);
            p |= (unsigned)c << (4 * n);
        }
        po[(rowbase + j) * D_ + d] = (float)p;
    }
}

// ---------------------------------------------------------------------------
// V quantization: group is the full head_dim (D=128), per (b,h,t). Packed along
// d (4 codes/u16), output transposed to (B,H,32,TQ). One warp per token row;
// lane loads float4 at d=4*lane -> lane owns exactly one packed uint16.
// ---------------------------------------------------------------------------
__global__ __launch_bounds__(256, 4)
void v_quant_kernel(const float* __restrict__ v, float* __restrict__ out) {
    const int g = blockIdx.x, h = blockIdx.y, b = blockIdx.z;
    const int lane = threadIdx.x & 31;
    const int warp = threadIdx.x >> 5;       // 8 warps

    __shared__ unsigned short sm[128][34];   // pitch 34: conflict-free transpose
    __shared__ float ssc[128];
    __shared__ float smin[128];

    const float* base = v + (((size_t)(b * H_ + h)) * S_ + (size_t)g * 128) * D_;

#pragma unroll 4
    for (int it = 0; it < 16; it++) {
        const int tl = warp * 16 + it;
        float4 x = *(const float4*)(base + (size_t)tl * D_ + lane * 4);
        float mn = fminf(fminf(x.x, x.y), fminf(x.z, x.w));
        float mx = fmaxf(fmaxf(x.x, x.y), fmaxf(x.z, x.w));
#pragma unroll
        for (int o = 16; o > 0; o >>= 1) {
            mn = fminf(mn, __shfl_xor_sync(0xFFFFFFFFu, mn, o));
            mx = fmaxf(mx, __shfl_xor_sync(0xFFFFFFFFu, mx, o));
        }
        const float scale = fmaxf(__fdiv_rn(mx - mn, 15.0f), 1e-6f);

        unsigned p = 0;
        {
            int c0 = (int)rintf(__fdiv_rn(x.x - mn, scale));
            int c1 = (int)rintf(__fdiv_rn(x.y - mn, scale));
            int c2 = (int)rintf(__fdiv_rn(x.z - mn, scale));
            int c3 = (int)rintf(__fdiv_rn(x.w - mn, scale));
            c0 = c0 < 0 ? 0 : (c0 > 15 ? 15 : c0);
            c1 = c1 < 0 ? 0 : (c1 > 15 ? 15 : c1);
            c2 = c2 < 0 ? 0 : (c2 > 15 ? 15 : c2);
            c3 = c3 < 0 ? 0 : (c3 > 15 ? 15 : c3);
            p = (unsigned)c0 | ((unsigned)c1 << 4) | ((unsigned)c2 << 8) | ((unsigned)c3 << 12);
        }
        sm[tl][lane] = (unsigned short)p;
        if (lane == 0) { ssc[tl] = scale; smin[tl] = mn; }
    }
    __syncthreads();

    // scale / min: contiguous along t, coalesced
    const size_t tbase = ((size_t)(b * H_ + h)) * TQ + (size_t)g * 128;
    for (int e = threadIdx.x; e < 128; e += 256) {
        out[OFF_VS + tbase + e] = ssc[e];
        out[OFF_VM + tbase + e] = smin[e];
    }

    // packed: (B,H,32,TQ) — rows d4, cols t. Coalesced along t.
    const size_t qvbase = ((size_t)(b * H_ + h)) * 32 * TQ;
#pragma unroll
    for (int e = threadIdx.x; e < 4096; e += 256) {
        const int d4 = e >> 7;
        const int tl = e & 127;
        out[OFF_QV + qvbase + (size_t)d4 * TQ + (size_t)g * 128 + tl] = (float)sm[tl][d4];
    }
}

// ---------------------------------------------------------------------------
// Residual buffers: (B,H,257,D); rows 0..127 = tail of k/v, rest zero. float4.
// ---------------------------------------------------------------------------
__global__ __launch_bounds__(256)
void resid_kernel(const float* __restrict__ k, const float* __restrict__ v,
                  float* __restrict__ out) {
    const int N4 = B_ * H_ * RROWS * (D_ / 4);   // 526,336
    int idx = blockIdx.x * 256 + threadIdx.x;
    if (idx >= N4) return;
    const int d4 = idx & 31;
    const int rest = idx >> 5;
    const int row = rest % RROWS;
    const int bh = rest / RROWS;

    float4 kv = make_float4(0.f, 0.f, 0.f, 0.f);
    float4 vv = make_float4(0.f, 0.f, 0.f, 0.f);
    if (row < 128) {
        const size_t si = (((size_t)bh) * S_ + TQ + row) * D_ + (size_t)d4 * 4;
        kv = *(const float4*)(k + si);
        vv = *(const float4*)(v + si);
    }
    ((float4*)(out + OFF_KR))[idx] = kv;
    ((float4*)(out + OFF_VR))[idx] = vv;
}

// ---------------------------------------------------------------------------
// Full caches: (B,H,S,D) zeros with k_new/v_new scattered at per-batch offset.
// float4 vectorized; one thread writes the matching k_full and v_full element.
// ---------------------------------------------------------------------------
__global__ __launch_bounds__(256)
void full_fill_kernel(const float* __restrict__ kn, const float* __restrict__ vn,
                      const int* __restrict__ cs, const int* __restrict__ qcs,
                      float* __restrict__ out) {
    const size_t idx = (size_t)blockIdx.x * 256 + threadIdx.x;  // per float4
    const size_t N4 = LEN_F / 4;                                 // 8,388,608
    if (idx >= N4) return;
    const int d4 = (int)(idx & 31);
    const size_t rest = idx >> 5;
    const int s = (int)(rest & (S_ - 1));
    const size_t bh = rest >> 12;           // S_ = 2^12
    const int b = (int)(bh >> 5);           // H_ = 32

    const int off = __ldg(cs + b) - __ldg(qcs + b);
    float4 kv = make_float4(0.f, 0.f, 0.f, 0.f);
    float4 vv = make_float4(0.f, 0.f, 0.f, 0.f);
    const int rs = s - off;
    if (rs >= 0 && rs < U_) {
        const size_t si = (bh * U_ + (size_t)rs) * D_ + (size_t)d4 * 4;
        kv = *(const float4*)(kn + si);
        vv = *(const float4*)(vn + si);
    }
    ((float4*)(out + OFF_KF))[idx] = kv;
    ((float4*)(out + OFF_VF))[idx] = vv;
}

// ---------------------------------------------------------------------------
extern "C" void kernel_launch(void* const* d_in, const int* in_sizes, int n_in,
                              void* d_out, int out_size) {
    const float* k     = (const float*)d_in[0];
    const float* v     = (const float*)d_in[1];
    const float* k_new = (const float*)d_in[2];
    const float* v_new = (const float*)d_in[3];
    const int*   cs    = (const int*)d_in[4];
    const int*   qcs   = (const int*)d_in[5];
    float* out = (float*)d_out;

    (void)in_sizes; (void)n_in; (void)out_size;

    dim3 qgrid(NG, H_, B_);
    k_quant_kernel<<<qgrid, 512>>>(k, out);
    v_quant_kernel<<<qgrid, 256>>>(v, out);

    const int rN4 = B_ * H_ * RROWS * (D_ / 4);
    resid_kernel<<<(rN4 + 255) / 256, 256>>>(k, v, out);

    const size_t fN4 = LEN_F / 4;
    full_fill_kernel<<<(unsigned)((fN4 + 255) / 256), 256>>>(k_new, v_new, cs, qcs, out);
}

// round 2
// speedup vs baseline: 1.1432x; 1.1432x over previous
#include <cuda_runtime.h>
#include <cstdint>

// Problem constants (fixed shapes per reference setup_inputs)
#define B_    2
#define H_    32
#define S_    4096
#define D_    128
#define U_    16
#define GROUP_ 128
#define TQ    3968        // S - RESID - (S % GROUP)
#define NG    31          // TQ / GROUP
#define RROWS 257         // 2*RESID + 1

// Output region offsets (float32 elements, concatenated in reference return order)
static constexpr size_t LEN_QK  = (size_t)B_ * H_ * (TQ / 4) * D_;   // 8,126,464
static constexpr size_t LEN_SC  = (size_t)B_ * H_ * NG * D_;         // 253,952
static constexpr size_t LEN_QV  = (size_t)B_ * H_ * (D_ / 4) * TQ;   // 8,126,464
static constexpr size_t LEN_VSC = (size_t)B_ * H_ * TQ;              // 253,952
static constexpr size_t LEN_R   = (size_t)B_ * H_ * RROWS * D_;      // 2,105,344
static constexpr size_t LEN_F   = (size_t)B_ * H_ * S_ * D_;         // 33,554,432

static constexpr size_t OFF_QK = 0;
static constexpr size_t OFF_KS = OFF_QK + LEN_QK;
static constexpr size_t OFF_KM = OFF_KS + LEN_SC;
static constexpr size_t OFF_QV = OFF_KM + LEN_SC;
static constexpr size_t OFF_VS = OFF_QV + LEN_QV;
static constexpr size_t OFF_VM = OFF_VS + LEN_VSC;
static constexpr size_t OFF_KR = OFF_VM + LEN_VSC;
static constexpr size_t OFF_VR = OFF_KR + LEN_R;
static constexpr size_t OFF_KF = OFF_VR + LEN_R;
static constexpr size_t OFF_VF = OFF_KF + LEN_F;

// ---------------------------------------------------------------------------
// K quantization: groups of 128 along seq, per (b,h,g,d). Pack 4 seq codes/u16.
// 512 threads: thread = (d2 in 0..63 [float2 over d], q in 0..7 [16 seq rows]).
// One divide per group-column instead of one per element.
// ---------------------------------------------------------------------------
__global__ __launch_bounds__(512, 2)
void k_quant_kernel(const float* __restrict__ k, float* __restrict__ out) {
    const int g = blockIdx.x, h = blockIdx.y, b = blockIdx.z;
    const int d2 = threadIdx.x & 63;         // float2 column: d = 2*d2
    const int q  = threadIdx.x >> 6;         // 0..7, each owns 16 seq rows
    const int bh = b * H_ + h;

    const float2* __restrict__ base = (const float2*)(
        k + (((size_t)bh) * S_ + (size_t)g * GROUP_) * D_) + d2;

    float2 vals[16];
    float mnx = 3.4e38f, mny = 3.4e38f, mxx = -3.4e38f, mxy = -3.4e38f;
#pragma unroll
    for (int i = 0; i < 16; i++) {
        float2 x = __ldg(base + (size_t)(q * 16 + i) * (D_ / 2));
        vals[i] = x;
        mnx = fminf(mnx, x.x); mny = fminf(mny, x.y);
        mxx = fmaxf(mxx, x.x); mxy = fmaxf(mxy, x.y);
    }

    __shared__ float2 smn[8][64];
    __shared__ float2 smx[8][64];
    smn[q][d2] = make_float2(mnx, mny);
    smx[q][d2] = make_float2(mxx, mxy);
    __syncthreads();
#pragma unroll
    for (int p = 0; p < 8; p++) {
        float2 a = smn[p][d2], bb = smx[p][d2];
        mnx = fminf(mnx, a.x); mny = fminf(mny, a.y);
        mxx = fmaxf(mxx, bb.x); mxy = fmaxf(mxy, bb.y);
    }

    const float scx = fmaxf(__fdiv_rn(mxx - mnx, 15.0f), 1e-6f);
    const float scy = fmaxf(__fdiv_rn(mxy - mny, 15.0f), 1e-6f);
    const float ivx = __fdiv_rn(1.0f, scx);
    const float ivy = __fdiv_rn(1.0f, scy);

    if (q == 0) {
        size_t si = (((size_t)bh) * NG + g) * D_ + 2 * d2;
        *(float2*)(out + OFF_KS + si) = make_float2(scx, scy);
        *(float2*)(out + OFF_KM + si) = make_float2(mnx, mny);
    }

    // pack: 4 packed rows per thread (each covers 4 of this thread's 16 seq rows)
    float* __restrict__ po = out + OFF_QK;
    const size_t rowbase = ((size_t)bh) * (TQ / 4) + (size_t)g * 32 + (size_t)q * 4;
#pragma unroll
    for (int j = 0; j < 4; j++) {
        unsigned px = 0, py = 0;
#pragma unroll
        for (int n = 0; n < 4; n++) {
            int cx = (int)rintf((vals[j * 4 + n].x - mnx) * ivx);
            int cy = (int)rintf((vals[j * 4 + n].y - mny) * ivy);
            cx = cx < 0 ? 0 : (cx > 15 ? 15 : cx);
            cy = cy < 0 ? 0 : (cy > 15 ? 15 : cy);
            px |= (unsigned)cx << (4 * n);
            py |= (unsigned)cy << (4 * n);
        }
        *(float2*)(po + (rowbase + j) * D_ + 2 * d2) = make_float2((float)px, (float)py);
    }
}

// ---------------------------------------------------------------------------
// V quantization: group is the full head_dim (D=128), per (b,h,t). Packed along
// d (4 codes/u16), output transposed to (B,H,32,TQ). One warp per token row;
// lane loads float4 at d=4*lane -> lane owns exactly one packed uint16.
// ---------------------------------------------------------------------------
__global__ __launch_bounds__(256, 4)
void v_quant_kernel(const float* __restrict__ v, float* __restrict__ out) {
    const int g = blockIdx.x, h = blockIdx.y, b = blockIdx.z;
    const int lane = threadIdx.x & 31;
    const int warp = threadIdx.x >> 5;       // 8 warps

    __shared__ unsigned short sm[128][34];   // pitch 34: conflict-free transpose
    __shared__ float ssc[128];
    __shared__ float smin[128];

    const float* base = v + (((size_t)(b * H_ + h)) * S_ + (size_t)g * 128) * D_;

#pragma unroll 4
    for (int it = 0; it < 16; it++) {
        const int tl = warp * 16 + it;
        float4 x = *(const float4*)(base + (size_t)tl * D_ + lane * 4);
        float mn = fminf(fminf(x.x, x.y), fminf(x.z, x.w));
        float mx = fmaxf(fmaxf(x.x, x.y), fmaxf(x.z, x.w));
#pragma unroll
        for (int o = 16; o > 0; o >>= 1) {
            mn = fminf(mn, __shfl_xor_sync(0xFFFFFFFFu, mn, o));
            mx = fmaxf(mx, __shfl_xor_sync(0xFFFFFFFFu, mx, o));
        }
        const float scale = fmaxf(__fdiv_rn(mx - mn, 15.0f), 1e-6f);
        const float inv   = __fdiv_rn(1.0f, scale);

        int c0 = (int)rintf((x.x - mn) * inv);
        int c1 = (int)rintf((x.y - mn) * inv);
        int c2 = (int)rintf((x.z - mn) * inv);
        int c3 = (int)rintf((x.w - mn) * inv);
        c0 = c0 < 0 ? 0 : (c0 > 15 ? 15 : c0);
        c1 = c1 < 0 ? 0 : (c1 > 15 ? 15 : c1);
        c2 = c2 < 0 ? 0 : (c2 > 15 ? 15 : c2);
        c3 = c3 < 0 ? 0 : (c3 > 15 ? 15 : c3);
        unsigned p = (unsigned)c0 | ((unsigned)c1 << 4) |
                     ((unsigned)c2 << 8) | ((unsigned)c3 << 12);

        sm[tl][lane] = (unsigned short)p;
        if (lane == 0) { ssc[tl] = scale; smin[tl] = mn; }
    }
    __syncthreads();

    // scale / min: contiguous along t, coalesced
    const size_t tbase = ((size_t)(b * H_ + h)) * TQ + (size_t)g * 128;
    for (int e = threadIdx.x; e < 128; e += 256) {
        out[OFF_VS + tbase + e] = ssc[e];
        out[OFF_VM + tbase + e] = smin[e];
    }

    // packed: (B,H,32,TQ) — rows d4, cols t. Coalesced along t.
    const size_t qvbase = ((size_t)(b * H_ + h)) * 32 * TQ;
#pragma unroll
    for (int e = threadIdx.x; e < 4096; e += 256) {
        const int d4 = e >> 7;
        const int tl = e & 127;
        out[OFF_QV + qvbase + (size_t)d4 * TQ + (size_t)g * 128 + tl] = (float)sm[tl][d4];
    }
}

// ---------------------------------------------------------------------------
// Residual data rows only (zeros are handled by the big memset). Writes the
// 128 tail rows of k/v into rows [0,128) of each (b,h) residual buffer.
// ---------------------------------------------------------------------------
__global__ __launch_bounds__(256)
void resid_copy_kernel(const float* __restrict__ k, const float* __restrict__ v,
                       float* __restrict__ out) {
    const int N4 = B_ * H_ * 128 * (D_ / 4);   // 262,144
    int idx = blockIdx.x * 256 + threadIdx.x;
    if (idx >= N4) return;
    const int d4  = idx & 31;
    const int row = (idx >> 5) & 127;
    const int bh  = idx >> 12;

    const size_t si = (((size_t)bh) * S_ + TQ + row) * D_ + (size_t)d4 * 4;
    const size_t di = (((size_t)bh) * RROWS + row) * D_ + (size_t)d4 * 4;
    *(float4*)(out + OFF_KR + di) = *(const float4*)(k + si);
    *(float4*)(out + OFF_VR + di) = *(const float4*)(v + si);
}

// ---------------------------------------------------------------------------
// Scatter k_new/v_new into the (already zeroed) full caches at per-batch offset.
// Tiny: B*H*U rows.
// ---------------------------------------------------------------------------
__global__ __launch_bounds__(256)
void scatter_new_kernel(const float* __restrict__ kn, const float* __restrict__ vn,
                        const int* __restrict__ cs, const int* __restrict__ qcs,
                        float* __restrict__ out) {
    const int N4 = B_ * H_ * U_ * (D_ / 4);    // 32,768
    int idx = blockIdx.x * 256 + threadIdx.x;
    if (idx >= N4) return;
    const int d4 = idx & 31;
    const int u  = (idx >> 5) & (U_ - 1);
    const int bh = idx >> 9;
    const int b  = bh >> 5;

    const int off = __ldg(cs + b) - __ldg(qcs + b);
    const size_t si = (((size_t)bh) * U_ + u) * D_ + (size_t)d4 * 4;
    const size_t di = (((size_t)bh) * S_ + (size_t)(off + u)) * D_ + (size_t)d4 * 4;
    *(float4*)(out + OFF_KF + di) = *(const float4*)(kn + si);
    *(float4*)(out + OFF_VF + di) = *(const float4*)(vn + si);
}

// ---------------------------------------------------------------------------
extern "C" void kernel_launch(void* const* d_in, const int* in_sizes, int n_in,
                              void* d_out, int out_size) {
    const float* k     = (const float*)d_in[0];
    const float* v     = (const float*)d_in[1];
    const float* k_new = (const float*)d_in[2];
    const float* v_new = (const float*)d_in[3];
    const int*   cs    = (const int*)d_in[4];
    const int*   qcs   = (const int*)d_in[5];
    float* out = (float*)d_out;

    (void)in_sizes; (void)n_in; (void)out_size;

    // Zero residual buffers + both full caches in one driver-optimized fill.
    // [OFF_KR, OFF_VF + LEN_F) is contiguous.
    const size_t zero_bytes = (2 * LEN_R + 2 * LEN_F) * sizeof(float);
    cudaMemsetAsync(out + OFF_KR, 0, zero_bytes);

    dim3 qgrid(NG, H_, B_);
    k_quant_kernel<<<qgrid, 512>>>(k, out);
    v_quant_kernel<<<qgrid, 256>>>(v, out);

    const int rN4 = B_ * H_ * 128 * (D_ / 4);
    resid_copy_kernel<<<(rN4 + 255) / 256, 256>>>(k, v, out);

    const int sN4 = B_ * H_ * U_ * (D_ / 4);
    scatter_new_kernel<<<(sN4 + 255) / 256, 256>>>(k_new, v_new, cs, qcs, out);
}

// round 3
// speedup vs baseline: 1.1704x; 1.0237x over previous
#include <cuda_runtime.h>
#include <cstdint>

// Problem constants (fixed shapes per reference setup_inputs)
#define B_    2
#define H_    32
#define S_    4096
#define D_    128
#define U_    16
#define TQ    3968        // S - RESID - (S % GROUP)
#define NG    31          // TQ / GROUP
#define RROWS 257         // 2*RESID + 1

// Output region offsets (float32 elements, concatenated in reference return order)
static constexpr size_t LEN_QK  = (size_t)B_ * H_ * (TQ / 4) * D_;   // 8,126,464
static constexpr size_t LEN_SC  = (size_t)B_ * H_ * NG * D_;         // 253,952
static constexpr size_t LEN_QV  = (size_t)B_ * H_ * (D_ / 4) * TQ;   // 8,126,464
static constexpr size_t LEN_VSC = (size_t)B_ * H_ * TQ;              // 253,952
static constexpr size_t LEN_R   = (size_t)B_ * H_ * RROWS * D_;      // 2,105,344
static constexpr size_t LEN_F   = (size_t)B_ * H_ * S_ * D_;         // 33,554,432 = 2^25

static constexpr size_t OFF_QK = 0;
static constexpr size_t OFF_KS = OFF_QK + LEN_QK;
static constexpr size_t OFF_KM = OFF_KS + LEN_SC;
static constexpr size_t OFF_QV = OFF_KM + LEN_SC;
static constexpr size_t OFF_VS = OFF_QV + LEN_QV;
static constexpr size_t OFF_VM = OFF_VS + LEN_VSC;
static constexpr size_t OFF_KR = OFF_VM + LEN_VSC;
static constexpr size_t OFF_VR = OFF_KR + LEN_R;
static constexpr size_t OFF_KF = OFF_VR + LEN_R;
static constexpr size_t OFF_VF = OFF_KF + LEN_F;

// Unified work list
static constexpr int    NK        = B_ * H_ * NG;                 // 1984 k-quant groups
static constexpr int    NV        = B_ * H_ * NG;                 // 1984 v-quant groups
static constexpr size_t FILL_F4   = (2 * LEN_R + 2 * LEN_F) / 4;  // 17,829,888 float4s
static constexpr int    FILL_CHUNK = 4096;                        // float4s per fill item (64 KB)
static constexpr int    NFILL     = (int)(FILL_F4 / FILL_CHUNK);  // 4353 (exact)
static constexpr int    NITEMS    = NK + NV + NFILL;              // 8321

static constexpr int GRID_ = 296;   // 2 CTAs/SM on 148 SMs

__global__ __launch_bounds__(512)
void mega_kernel(const float* __restrict__ k, const float* __restrict__ v,
                 const float* __restrict__ kn, const float* __restrict__ vn,
                 const int* __restrict__ cs, const int* __restrict__ qcs,
                 float* __restrict__ out)
{
    __shared__ float2 smn[8][64];
    __shared__ float2 smx[8][64];
    __shared__ unsigned short smq[128][34];   // pitch 34: conflict-free transpose
    __shared__ float ssc[128];
    __shared__ float smin[128];

    const int tid = threadIdx.x;

    for (int item = blockIdx.x; item < NITEMS; item += GRID_) {
        if (item < NK) {
            // ---------------- K quant: group of 128 seq rows, per (b,h,g,d) ----
            __syncthreads();   // protect smn/smx reuse across items
            const int bh = item / NG;
            const int g  = item - bh * NG;
            const int d2 = tid & 63;          // float2 column, d = 2*d2
            const int q  = tid >> 6;          // 0..7, each owns 16 seq rows

            const float2* __restrict__ base = (const float2*)(
                k + (((size_t)bh) * S_ + (size_t)g * 128) * D_) + d2;

            float2 vals[16];
            float mnx = 3.4e38f, mny = 3.4e38f, mxx = -3.4e38f, mxy = -3.4e38f;
#pragma unroll
            for (int i = 0; i < 16; i++) {
                float2 x = __ldg(base + (size_t)(q * 16 + i) * (D_ / 2));
                vals[i] = x;
                mnx = fminf(mnx, x.x); mny = fminf(mny, x.y);
                mxx = fmaxf(mxx, x.x); mxy = fmaxf(mxy, x.y);
            }
            smn[q][d2] = make_float2(mnx, mny);
            smx[q][d2] = make_float2(mxx, mxy);
            __syncthreads();
#pragma unroll
            for (int p = 0; p < 8; p++) {
                float2 a = smn[p][d2], bb = smx[p][d2];
                mnx = fminf(mnx, a.x); mny = fminf(mny, a.y);
                mxx = fmaxf(mxx, bb.x); mxy = fmaxf(mxy, bb.y);
            }
            const float scx = fmaxf(__fdiv_rn(mxx - mnx, 15.0f), 1e-6f);
            const float scy = fmaxf(__fdiv_rn(mxy - mny, 15.0f), 1e-6f);
            const float ivx = __fdiv_rn(1.0f, scx);
            const float ivy = __fdiv_rn(1.0f, scy);

            if (q == 0) {
                size_t si = (((size_t)bh) * NG + g) * D_ + 2 * d2;
                *(float2*)(out + OFF_KS + si) = make_float2(scx, scy);
                *(float2*)(out + OFF_KM + si) = make_float2(mnx, mny);
            }

            float* __restrict__ po = out + OFF_QK;
            const size_t rowbase = ((size_t)bh) * (TQ / 4) + (size_t)g * 32 + (size_t)q * 4;
#pragma unroll
            for (int j = 0; j < 4; j++) {
                unsigned px = 0, py = 0;
#pragma unroll
                for (int n = 0; n < 4; n++) {
                    int cx = (int)rintf((vals[j * 4 + n].x - mnx) * ivx);
                    int cy = (int)rintf((vals[j * 4 + n].y - mny) * ivy);
                    cx = cx < 0 ? 0 : (cx > 15 ? 15 : cx);
                    cy = cy < 0 ? 0 : (cy > 15 ? 15 : cy);
                    px |= (unsigned)cx << (4 * n);
                    py |= (unsigned)cy << (4 * n);
                }
                *(float2*)(po + (rowbase + j) * D_ + 2 * d2) =
                    make_float2((float)px, (float)py);
            }
        } else if (item < NK + NV) {
            // ---------------- V quant: group = full head_dim, per token --------
            __syncthreads();   // protect smq/ssc/smin reuse across items
            const int vi = item - NK;
            const int bh = vi / NG;
            const int g  = vi - bh * NG;
            const int lane = tid & 31;
            const int warp = tid >> 5;       // 16 warps, 8 tokens each

            const float* __restrict__ base =
                v + (((size_t)bh) * S_ + (size_t)g * 128) * D_;

#pragma unroll 2
            for (int it = 0; it < 8; it++) {
                const int tl = warp * 8 + it;
                float4 x = *(const float4*)(base + (size_t)tl * D_ + lane * 4);
                float mn = fminf(fminf(x.x, x.y), fminf(x.z, x.w));
                float mx = fmaxf(fmaxf(x.x, x.y), fmaxf(x.z, x.w));
#pragma unroll
                for (int o = 16; o > 0; o >>= 1) {
                    mn = fminf(mn, __shfl_xor_sync(0xFFFFFFFFu, mn, o));
                    mx = fmaxf(mx, __shfl_xor_sync(0xFFFFFFFFu, mx, o));
                }
                const float scale = fmaxf(__fdiv_rn(mx - mn, 15.0f), 1e-6f);
                const float inv   = __fdiv_rn(1.0f, scale);

                int c0 = (int)rintf((x.x - mn) * inv);
                int c1 = (int)rintf((x.y - mn) * inv);
                int c2 = (int)rintf((x.z - mn) * inv);
                int c3 = (int)rintf((x.w - mn) * inv);
                c0 = c0 < 0 ? 0 : (c0 > 15 ? 15 : c0);
                c1 = c1 < 0 ? 0 : (c1 > 15 ? 15 : c1);
                c2 = c2 < 0 ? 0 : (c2 > 15 ? 15 : c2);
                c3 = c3 < 0 ? 0 : (c3 > 15 ? 15 : c3);
                smq[tl][lane] = (unsigned short)((unsigned)c0 | ((unsigned)c1 << 4) |
                                                ((unsigned)c2 << 8) | ((unsigned)c3 << 12));
                if (lane == 0) { ssc[tl] = scale; smin[tl] = mn; }
            }
            __syncthreads();

            const size_t tbase = ((size_t)bh) * TQ + (size_t)g * 128;
            if (tid < 128) {
                out[OFF_VS + tbase + tid] = ssc[tid];
                out[OFF_VM + tbase + tid] = smin[tid];
            }
            const size_t qvbase = ((size_t)bh) * 32 * TQ;
#pragma unroll
            for (int e = tid; e < 4096; e += 512) {
                const int d4 = e >> 7;
                const int tl = e & 127;
                out[OFF_QV + qvbase + (size_t)d4 * TQ + (size_t)g * 128 + tl] =
                    (float)smq[tl][d4];
            }
        } else {
            // ---------------- Fill: zeros + residual tails + new-token scatter --
            const int fitem = item - NK - NV;
            const size_t base4 = (size_t)fitem * FILL_CHUNK;
            const int off0 = __ldg(cs + 0) - __ldg(qcs + 0);
            const int off1 = __ldg(cs + 1) - __ldg(qcs + 1);
            float4* __restrict__ dst = (float4*)(out + OFF_KR);

#pragma unroll
            for (int j = 0; j < FILL_CHUNK / 512; j++) {
                const size_t f  = base4 + tid + (size_t)j * 512;
                const size_t fi = f * 4;   // float offset within fill region
                float4 val = make_float4(0.f, 0.f, 0.f, 0.f);
                if (fi < 2 * LEN_R) {
                    // residual buffers (B,H,257,D): rows 0..127 copy tail, rest 0
                    const int  half = fi >= LEN_R;
                    const size_t r  = fi - (half ? LEN_R : 0);
                    const int  bh   = (int)(r / (RROWS * D_));
                    const int  rr   = (int)(r - (size_t)bh * (RROWS * D_));
                    const int  row  = rr >> 7;
                    const int  d    = rr & 127;
                    if (row < 128) {
                        const float* __restrict__ src = half ? v : k;
                        val = *(const float4*)(src + (((size_t)bh) * S_ + TQ + row) * D_ + d);
                    }
                } else {
                    // full caches (B,H,S,D): zeros + k_new/v_new at per-batch off
                    const size_t fi2 = fi - 2 * LEN_R;
                    const int  half  = (int)(fi2 >> 25);       // LEN_F = 2^25
                    const size_t r   = fi2 & (LEN_F - 1);
                    const int  bh    = (int)(r >> 19);         // S_*D_ = 2^19
                    const int  s     = (int)((r >> 7) & (S_ - 1));
                    const int  d     = (int)(r & 127);
                    const int  b     = bh >> 5;                // H_ = 32
                    const int  u     = s - (b ? off1 : off0);
                    if ((unsigned)u < (unsigned)U_) {
                        const float* __restrict__ src = half ? vn : kn;
                        val = *(const float4*)(src + (((size_t)bh) * U_ + u) * D_ + d);
                    }
                }
                dst[f] = val;
            }
        }
    }
}

// ---------------------------------------------------------------------------
extern "C" void kernel_launch(void* const* d_in, const int* in_sizes, int n_in,
                              void* d_out, int out_size) {
    const float* k     = (const float*)d_in[0];
    const float* v     = (const float*)d_in[1];
    const float* k_new = (const float*)d_in[2];
    const float* v_new = (const float*)d_in[3];
    const int*   cs    = (const int*)d_in[4];
    const int*   qcs   = (const int*)d_in[5];
    float* out = (float*)d_out;

    (void)in_sizes; (void)n_in; (void)out_size;

    mega_kernel<<<GRID_, 512>>>(k, v, k_new, v_new, cs, qcs, out);
}